// round 2
// baseline (speedup 1.0000x reference)
#include <cuda_runtime.h>

#define F_IN 512
#define H1   8
#define C1   8
#define D1   64      // H1*C1
#define OUT  40
#define NMAX 100000

// ---------------- scratch (device globals: allocation-free) ----------------
__device__ __align__(16) float g_h1 [NMAX * D1];   // layer1 features x@W1  [N,64]
__device__ __align__(16) float g_as1[NMAX * H1];   // alpha_src per node/head
__device__ __align__(16) float g_ad1[NMAX * H1];   // alpha_dst per node/head
__device__ __align__(16) float g_den1[NMAX * H1];  // softmax denominators
__device__ __align__(16) float g_acc1[NMAX * D1];  // un-normalized aggregation
__device__ __align__(16) float g_h2 [NMAX * D1];   // elu(layer1 out)
__device__ __align__(16) float g_g2 [NMAX * OUT];  // layer2 features h2@W2 [N,40]
__device__ __align__(16) float g_as2[NMAX];
__device__ __align__(16) float g_ad2[NMAX];
__device__ __align__(16) float g_den2[NMAX];

// ---------------- init: zero accumulators + output ----------------
__global__ void init_kernel(float* __restrict__ out, int N) {
    int i = blockIdx.x * blockDim.x + threadIdx.x;
    int stride = gridDim.x * blockDim.x;
    for (int t = i; t < N * D1;  t += stride) g_acc1[t] = 0.0f;
    for (int t = i; t < N * H1;  t += stride) g_den1[t] = 0.0f;
    for (int t = i; t < N;       t += stride) g_den2[t] = 0.0f;
    for (int t = i; t < N * OUT; t += stride) out[t]    = 0.0f;
}

// ---------------- GEMM1: h1[N,64] = x[N,512] @ W1[512,64] ----------------
// 128x64 block tile, BK=32, 256 threads, 8x4 per-thread microtile.
__global__ __launch_bounds__(256)
void gemm1_kernel(const float* __restrict__ x, const float* __restrict__ W, int N) {
    __shared__ float sx[128][33];   // padded to kill bank conflicts
    __shared__ float sw[32][64];

    int tid  = threadIdx.x;
    int row0 = blockIdx.x * 128;
    int tx = tid & 15;              // 16 col groups of 4
    int ty = tid >> 4;              // 16 row groups of 8

    float acc[8][4];
#pragma unroll
    for (int i = 0; i < 8; i++)
#pragma unroll
        for (int j = 0; j < 4; j++) acc[i][j] = 0.0f;

    int xcg = (tid & 7) * 4;        // x-load col group
    int xr  = tid >> 3;             // x-load row base (0..31)
    int wc  = (tid & 15) * 4;       // W-load cols
    int wk  = tid >> 4;             // W-load row base (0..15)

    for (int k0 = 0; k0 < F_IN; k0 += 32) {
        // load x tile [128x32]
#pragma unroll
        for (int rr = 0; rr < 4; rr++) {
            int row  = xr + rr * 32;
            int grow = row0 + row;
            float4 v = make_float4(0.f, 0.f, 0.f, 0.f);
            if (grow < N)
                v = *(const float4*)&x[(size_t)grow * F_IN + k0 + xcg];
            sx[row][xcg + 0] = v.x; sx[row][xcg + 1] = v.y;
            sx[row][xcg + 2] = v.z; sx[row][xcg + 3] = v.w;
        }
        // load W tile [32x64]
#pragma unroll
        for (int p = 0; p < 2; p++) {
            int k = wk + p * 16;
            float4 v = *(const float4*)&W[(size_t)(k0 + k) * D1 + wc];
            sw[k][wc + 0] = v.x; sw[k][wc + 1] = v.y;
            sw[k][wc + 2] = v.z; sw[k][wc + 3] = v.w;
        }
        __syncthreads();

#pragma unroll
        for (int kk = 0; kk < 32; kk++) {
            float a[8], b[4];
#pragma unroll
            for (int i = 0; i < 8; i++) a[i] = sx[ty * 8 + i][kk];
#pragma unroll
            for (int j = 0; j < 4; j++) b[j] = sw[kk][tx * 4 + j];
#pragma unroll
            for (int i = 0; i < 8; i++)
#pragma unroll
                for (int j = 0; j < 4; j++) acc[i][j] += a[i] * b[j];
        }
        __syncthreads();
    }

#pragma unroll
    for (int i = 0; i < 8; i++) {
        int grow = row0 + ty * 8 + i;
        if (grow < N) {
#pragma unroll
            for (int j = 0; j < 4; j++)
                g_h1[(size_t)grow * D1 + tx * 4 + j] = acc[i][j];
        }
    }
}

// ---------------- alpha1: per (node, head) dot products ----------------
__global__ void alpha1_kernel(const float* __restrict__ a_src,
                              const float* __restrict__ a_dst, int N) {
    int i = blockIdx.x * blockDim.x + threadIdx.x;
    if (i >= N * H1) return;
    int h = i & 7;
    const float4* hp = (const float4*)&g_h1[(size_t)(i >> 3) * D1 + h * 8];
    float4 v0 = hp[0], v1 = hp[1];
    const float4* asv = (const float4*)&a_src[h * 8];
    const float4* adv = (const float4*)&a_dst[h * 8];
    float4 s0 = asv[0], s1 = asv[1];
    float4 d0 = adv[0], d1 = adv[1];
    g_as1[i] = v0.x * s0.x + v0.y * s0.y + v0.z * s0.z + v0.w * s0.w
             + v1.x * s1.x + v1.y * s1.y + v1.z * s1.z + v1.w * s1.w;
    g_ad1[i] = v0.x * d0.x + v0.y * d0.y + v0.z * d0.z + v0.w * d0.w
             + v1.x * d1.x + v1.y * d1.y + v1.z * d1.z + v1.w * d1.w;
}

// ---------------- edge pass, layer 1: 8 threads per edge (one per head) ----
__global__ __launch_bounds__(256)
void edge1_kernel(const int* __restrict__ ei, int E, int Etot) {
    int idx = blockIdx.x * blockDim.x + threadIdx.x;
    int e = idx >> 3;
    if (e >= Etot) return;
    int h = idx & 7;
    int s, d;
    if (e < E) { s = ei[e]; d = ei[E + e]; }
    else       { s = e - E; d = s; }

    float t = g_as1[s * H1 + h] + g_ad1[d * H1 + h];
    t = (t > 0.0f) ? t : 0.2f * t;            // leaky_relu
    float ex = __expf(t);                     // no max-shift needed (bounded)

    atomicAdd(&g_den1[d * H1 + h], ex);

    const float4* hp = (const float4*)&g_h1[(size_t)s * D1 + h * 8];
    float4 v0 = hp[0], v1 = hp[1];
    float* ap = &g_acc1[(size_t)d * D1 + h * 8];
    atomicAdd(ap + 0, ex * v0.x); atomicAdd(ap + 1, ex * v0.y);
    atomicAdd(ap + 2, ex * v0.z); atomicAdd(ap + 3, ex * v0.w);
    atomicAdd(ap + 4, ex * v1.x); atomicAdd(ap + 5, ex * v1.y);
    atomicAdd(ap + 6, ex * v1.z); atomicAdd(ap + 7, ex * v1.w);
}

// ---------------- node finalize layer1: divide, +bias, ELU ----------------
__global__ void node1_kernel(const float* __restrict__ b1, int N) {
    int i = blockIdx.x * blockDim.x + threadIdx.x;
    if (i >= N * D1) return;
    int c = i & (D1 - 1);
    int n = i >> 6;
    float v = g_acc1[i] / (g_den1[n * H1 + (c >> 3)] + 1e-16f) + b1[c];
    g_h2[i] = (v > 0.0f) ? v : (__expf(v) - 1.0f);   // ELU
}

// ---------------- GEMM2 + alpha2: g2[N,40] = h2[N,64]@W2[64,40] ------------
// 64 nodes per block, 256 threads; thread (r = tid/4, q = tid&3) does 10 cols.
__global__ __launch_bounds__(256)
void gemm2_kernel(const float* __restrict__ W2,
                  const float* __restrict__ a_src2,
                  const float* __restrict__ a_dst2, int N) {
    __shared__ float sh[64 * 65];       // h2 tile, padded rows
    __shared__ float sw2[64 * OUT];     // W2

    int tid = threadIdx.x;
    int n0  = blockIdx.x * 64;

    for (int t = tid; t < 64 * D1; t += 256) {
        int r = t >> 6, c = t & 63;
        int gn = n0 + r;
        sh[r * 65 + c] = (gn < N) ? g_h2[(size_t)gn * D1 + c] : 0.0f;
    }
    for (int t = tid; t < D1 * OUT; t += 256) sw2[t] = W2[t];
    __syncthreads();

    int r = tid >> 2;        // node row 0..63
    int q = tid & 3;         // col group 0..3 (10 cols each)
    float acc[10];
#pragma unroll
    for (int j = 0; j < 10; j++) acc[j] = 0.0f;

#pragma unroll 8
    for (int k = 0; k < D1; k++) {
        float a = sh[r * 65 + k];
#pragma unroll
        for (int j = 0; j < 10; j++)
            acc[j] += a * sw2[k * OUT + q * 10 + j];
    }

    int gn = n0 + r;
    float ps = 0.0f, pd = 0.0f;
#pragma unroll
    for (int j = 0; j < 10; j++) {
        int c = q * 10 + j;
        ps += acc[j] * __ldg(&a_src2[c]);
        pd += acc[j] * __ldg(&a_dst2[c]);
        if (gn < N) g_g2[(size_t)gn * OUT + c] = acc[j];
    }
    // reduce across the 4 threads of this node (consecutive lanes)
    ps += __shfl_down_sync(0xffffffffu, ps, 1, 4);
    ps += __shfl_down_sync(0xffffffffu, ps, 2, 4);
    pd += __shfl_down_sync(0xffffffffu, pd, 1, 4);
    pd += __shfl_down_sync(0xffffffffu, pd, 2, 4);
    if (q == 0 && gn < N) { g_as2[gn] = ps; g_ad2[gn] = pd; }
}

// ---------------- edge pass, layer 2: 8 threads/edge, 5 cols each ----------
__global__ __launch_bounds__(256)
void edge2_kernel(const int* __restrict__ ei, int E, int Etot,
                  float* __restrict__ out) {
    int idx = blockIdx.x * blockDim.x + threadIdx.x;
    int e = idx >> 3;
    if (e >= Etot) return;
    int j = idx & 7;
    int s, d;
    if (e < E) { s = ei[e]; d = ei[E + e]; }
    else       { s = e - E; d = s; }

    float t = g_as2[s] + g_ad2[d];
    t = (t > 0.0f) ? t : 0.2f * t;
    float ex = __expf(t);

    if (j == 0) atomicAdd(&g_den2[d], ex);

    const float* gp = &g_g2[(size_t)s * OUT + j * 5];
    float* op = &out[(size_t)d * OUT + j * 5];
#pragma unroll
    for (int jj = 0; jj < 5; jj++)
        atomicAdd(op + jj, ex * gp[jj]);
}

// ---------------- finalize output ----------------
__global__ void final_kernel(const float* __restrict__ b2, float* __restrict__ out,
                             int N) {
    int i = blockIdx.x * blockDim.x + threadIdx.x;
    if (i >= N * OUT) return;
    int n = i / OUT;
    int c = i - n * OUT;
    out[i] = out[i] / (g_den2[n] + 1e-16f) + b2[c];
}

// ---------------- launch ----------------
extern "C" void kernel_launch(void* const* d_in, const int* in_sizes, int n_in,
                              void* d_out, int out_size) {
    const float* x      = (const float*)d_in[0];
    const int*   ei     = (const int*)d_in[1];   // JAX x64 disabled -> int32
    const float* W1     = (const float*)d_in[2];
    const float* a_src1 = (const float*)d_in[3];
    const float* a_dst1 = (const float*)d_in[4];
    const float* b1     = (const float*)d_in[5];
    const float* W2     = (const float*)d_in[6];
    const float* a_src2 = (const float*)d_in[7];
    const float* a_dst2 = (const float*)d_in[8];
    const float* b2     = (const float*)d_in[9];
    float* out = (float*)d_out;

    int N    = in_sizes[0] / F_IN;       // 100000
    int E    = in_sizes[1] / 2;          // 3200000
    int Etot = E + N;                    // + self loops

    init_kernel<<<2048, 256>>>(out, N);

    gemm1_kernel<<<(N + 127) / 128, 256>>>(x, W1, N);

    alpha1_kernel<<<(N * H1 + 255) / 256, 256>>>(a_src1, a_dst1, N);

    edge1_kernel<<<(Etot * 8 + 255) / 256, 256>>>(ei, E, Etot);

    node1_kernel<<<(N * D1 + 255) / 256, 256>>>(b1, N);

    gemm2_kernel<<<(N + 63) / 64, 256>>>(W2, a_src2, a_dst2, N);

    edge2_kernel<<<(Etot * 8 + 255) / 256, 256>>>(ei, E, Etot, out);

    final_kernel<<<(N * OUT + 255) / 256, 256>>>(b2, out, N);
}

// round 3
// speedup vs baseline: 1.3948x; 1.3948x over previous
#include <cuda_runtime.h>

#define F_IN 512
#define H1   8
#define C1   8
#define D1   64      // H1*C1
#define OUT  40
#define NMAX 100000

// ---------------- scratch (device globals: allocation-free) ----------------
__device__ __align__(16) float g_h1 [NMAX * D1];   // layer1 features x@W1  [N,64]
__device__ __align__(16) float g_as1[NMAX * H1];   // alpha_src per node/head
__device__ __align__(16) float g_ad1[NMAX * H1];   // alpha_dst per node/head
__device__ __align__(16) float g_den1[NMAX * H1];  // softmax denominators
__device__ __align__(16) float g_acc1[NMAX * D1];  // un-normalized aggregation
__device__ __align__(16) float g_h2 [NMAX * D1];   // elu(layer1 out)
__device__ __align__(16) float g_g2 [NMAX * OUT];  // layer2 features h2@W2 [N,40]
__device__ __align__(16) float g_as2[NMAX];
__device__ __align__(16) float g_ad2[NMAX];
__device__ __align__(16) float g_den2[NMAX];

// vectorized global reduction (sm_90+): one L1tex op for 16 bytes
__device__ __forceinline__ void red_add_v4(float* p, float a, float b, float c, float d) {
    asm volatile("red.global.add.v4.f32 [%0], {%1, %2, %3, %4};"
                 :: "l"(p), "f"(a), "f"(b), "f"(c), "f"(d) : "memory");
}

// ---------------- init: zero accumulators + output ----------------
__global__ void init_kernel(float* __restrict__ out, int N) {
    int i = blockIdx.x * blockDim.x + threadIdx.x;
    int stride = gridDim.x * blockDim.x;
    for (int t = i; t < N * D1;  t += stride) g_acc1[t] = 0.0f;
    for (int t = i; t < N * H1;  t += stride) g_den1[t] = 0.0f;
    for (int t = i; t < N;       t += stride) g_den2[t] = 0.0f;
    for (int t = i; t < N * OUT; t += stride) out[t]    = 0.0f;
}

// ---------------- GEMM1: h1[N,64] = x[N,512] @ W1[512,64] ----------------
__global__ __launch_bounds__(256)
void gemm1_kernel(const float* __restrict__ x, const float* __restrict__ W, int N) {
    __shared__ float sx[128][33];
    __shared__ float sw[32][64];

    int tid  = threadIdx.x;
    int row0 = blockIdx.x * 128;
    int tx = tid & 15;
    int ty = tid >> 4;

    float acc[8][4];
#pragma unroll
    for (int i = 0; i < 8; i++)
#pragma unroll
        for (int j = 0; j < 4; j++) acc[i][j] = 0.0f;

    int xcg = (tid & 7) * 4;
    int xr  = tid >> 3;
    int wc  = (tid & 15) * 4;
    int wk  = tid >> 4;

    for (int k0 = 0; k0 < F_IN; k0 += 32) {
#pragma unroll
        for (int rr = 0; rr < 4; rr++) {
            int row  = xr + rr * 32;
            int grow = row0 + row;
            float4 v = make_float4(0.f, 0.f, 0.f, 0.f);
            if (grow < N)
                v = *(const float4*)&x[(size_t)grow * F_IN + k0 + xcg];
            sx[row][xcg + 0] = v.x; sx[row][xcg + 1] = v.y;
            sx[row][xcg + 2] = v.z; sx[row][xcg + 3] = v.w;
        }
#pragma unroll
        for (int p = 0; p < 2; p++) {
            int k = wk + p * 16;
            float4 v = *(const float4*)&W[(size_t)(k0 + k) * D1 + wc];
            sw[k][wc + 0] = v.x; sw[k][wc + 1] = v.y;
            sw[k][wc + 2] = v.z; sw[k][wc + 3] = v.w;
        }
        __syncthreads();

#pragma unroll
        for (int kk = 0; kk < 32; kk++) {
            float a[8], b[4];
#pragma unroll
            for (int i = 0; i < 8; i++) a[i] = sx[ty * 8 + i][kk];
#pragma unroll
            for (int j = 0; j < 4; j++) b[j] = sw[kk][tx * 4 + j];
#pragma unroll
            for (int i = 0; i < 8; i++)
#pragma unroll
                for (int j = 0; j < 4; j++) acc[i][j] += a[i] * b[j];
        }
        __syncthreads();
    }

#pragma unroll
    for (int i = 0; i < 8; i++) {
        int grow = row0 + ty * 8 + i;
        if (grow < N) {
#pragma unroll
            for (int j = 0; j < 4; j++)
                g_h1[(size_t)grow * D1 + tx * 4 + j] = acc[i][j];
        }
    }
}

// ---------------- alpha1: per (node, head) dot products ----------------
__global__ void alpha1_kernel(const float* __restrict__ a_src,
                              const float* __restrict__ a_dst, int N) {
    int i = blockIdx.x * blockDim.x + threadIdx.x;
    if (i >= N * H1) return;
    int h = i & 7;
    const float4* hp = (const float4*)&g_h1[(size_t)(i >> 3) * D1 + h * 8];
    float4 v0 = hp[0], v1 = hp[1];
    const float4* asv = (const float4*)&a_src[h * 8];
    const float4* adv = (const float4*)&a_dst[h * 8];
    float4 s0 = asv[0], s1 = asv[1];
    float4 d0 = adv[0], d1 = adv[1];
    g_as1[i] = v0.x * s0.x + v0.y * s0.y + v0.z * s0.z + v0.w * s0.w
             + v1.x * s1.x + v1.y * s1.y + v1.z * s1.z + v1.w * s1.w;
    g_ad1[i] = v0.x * d0.x + v0.y * d0.y + v0.z * d0.z + v0.w * d0.w
             + v1.x * d1.x + v1.y * d1.y + v1.z * d1.z + v1.w * d1.w;
}

// ---------------- edge pass, layer 1: 8 threads per edge (one per head) ----
__global__ __launch_bounds__(256)
void edge1_kernel(const int* __restrict__ ei, int E, int Etot) {
    int idx = blockIdx.x * blockDim.x + threadIdx.x;
    int e = idx >> 3;
    if (e >= Etot) return;
    int h = idx & 7;
    int s, d;
    if (e < E) { s = ei[e]; d = ei[E + e]; }
    else       { s = e - E; d = s; }

    float t = g_as1[s * H1 + h] + g_ad1[d * H1 + h];
    t = (t > 0.0f) ? t : 0.2f * t;            // leaky_relu
    float ex = __expf(t);                     // no max-shift needed (bounded)

    atomicAdd(&g_den1[d * H1 + h], ex);

    const float4* hp = (const float4*)&g_h1[(size_t)s * D1 + h * 8];
    float4 v0 = hp[0], v1 = hp[1];
    float* ap = &g_acc1[(size_t)d * D1 + h * 8];
    red_add_v4(ap + 0, ex * v0.x, ex * v0.y, ex * v0.z, ex * v0.w);
    red_add_v4(ap + 4, ex * v1.x, ex * v1.y, ex * v1.z, ex * v1.w);
}

// ---------------- node finalize layer1: divide, +bias, ELU ----------------
__global__ void node1_kernel(const float* __restrict__ b1, int N) {
    int i = blockIdx.x * blockDim.x + threadIdx.x;
    if (i >= N * D1) return;
    int c = i & (D1 - 1);
    int n = i >> 6;
    float v = g_acc1[i] / (g_den1[n * H1 + (c >> 3)] + 1e-16f) + b1[c];
    g_h2[i] = (v > 0.0f) ? v : (__expf(v) - 1.0f);   // ELU
}

// ---------------- GEMM2 + alpha2: g2[N,40] = h2[N,64]@W2[64,40] ------------
__global__ __launch_bounds__(256)
void gemm2_kernel(const float* __restrict__ W2,
                  const float* __restrict__ a_src2,
                  const float* __restrict__ a_dst2, int N) {
    __shared__ float sh[64 * 65];
    __shared__ float sw2[64 * OUT];

    int tid = threadIdx.x;
    int n0  = blockIdx.x * 64;

    for (int t = tid; t < 64 * D1; t += 256) {
        int r = t >> 6, c = t & 63;
        int gn = n0 + r;
        sh[r * 65 + c] = (gn < N) ? g_h2[(size_t)gn * D1 + c] : 0.0f;
    }
    for (int t = tid; t < D1 * OUT; t += 256) sw2[t] = W2[t];
    __syncthreads();

    int r = tid >> 2;
    int q = tid & 3;
    float acc[10];
#pragma unroll
    for (int j = 0; j < 10; j++) acc[j] = 0.0f;

#pragma unroll 8
    for (int k = 0; k < D1; k++) {
        float a = sh[r * 65 + k];
#pragma unroll
        for (int j = 0; j < 10; j++)
            acc[j] += a * sw2[k * OUT + q * 10 + j];
    }

    int gn = n0 + r;
    float ps = 0.0f, pd = 0.0f;
#pragma unroll
    for (int j = 0; j < 10; j++) {
        int c = q * 10 + j;
        ps += acc[j] * __ldg(&a_src2[c]);
        pd += acc[j] * __ldg(&a_dst2[c]);
        if (gn < N) g_g2[(size_t)gn * OUT + c] = acc[j];
    }
    ps += __shfl_down_sync(0xffffffffu, ps, 1, 4);
    ps += __shfl_down_sync(0xffffffffu, ps, 2, 4);
    pd += __shfl_down_sync(0xffffffffu, pd, 1, 4);
    pd += __shfl_down_sync(0xffffffffu, pd, 2, 4);
    if (q == 0 && gn < N) { g_as2[gn] = ps; g_ad2[gn] = pd; }
}

// ---------------- edge pass, layer 2: 10 threads/edge, 4 cols each ---------
// 40 = 10*4 -> every thread does one float4 load + one red.v4 (16B aligned).
__global__ __launch_bounds__(256)
void edge2_kernel(const int* __restrict__ ei, int E, int Etot,
                  float* __restrict__ out) {
    int idx = blockIdx.x * blockDim.x + threadIdx.x;
    int e = idx / 10;
    if (e >= Etot) return;
    int j = idx - e * 10;
    int s, d;
    if (e < E) { s = ei[e]; d = ei[E + e]; }
    else       { s = e - E; d = s; }

    float t = g_as2[s] + g_ad2[d];
    t = (t > 0.0f) ? t : 0.2f * t;
    float ex = __expf(t);

    if (j == 0) atomicAdd(&g_den2[d], ex);

    float4 v = *(const float4*)&g_g2[(size_t)s * OUT + j * 4];
    red_add_v4(&out[(size_t)d * OUT + j * 4],
               ex * v.x, ex * v.y, ex * v.z, ex * v.w);
}

// ---------------- finalize output ----------------
__global__ void final_kernel(const float* __restrict__ b2, float* __restrict__ out,
                             int N) {
    int i = blockIdx.x * blockDim.x + threadIdx.x;
    if (i >= N * OUT) return;
    int n = i / OUT;
    int c = i - n * OUT;
    out[i] = out[i] / (g_den2[n] + 1e-16f) + b2[c];
}

// ---------------- launch ----------------
extern "C" void kernel_launch(void* const* d_in, const int* in_sizes, int n_in,
                              void* d_out, int out_size) {
    const float* x      = (const float*)d_in[0];
    const int*   ei     = (const int*)d_in[1];   // int32 edge index
    const float* W1     = (const float*)d_in[2];
    const float* a_src1 = (const float*)d_in[3];
    const float* a_dst1 = (const float*)d_in[4];
    const float* b1     = (const float*)d_in[5];
    const float* W2     = (const float*)d_in[6];
    const float* a_src2 = (const float*)d_in[7];
    const float* a_dst2 = (const float*)d_in[8];
    const float* b2     = (const float*)d_in[9];
    float* out = (float*)d_out;

    int N    = in_sizes[0] / F_IN;       // 100000
    int E    = in_sizes[1] / 2;          // 3200000
    int Etot = E + N;                    // + self loops

    init_kernel<<<2048, 256>>>(out, N);

    gemm1_kernel<<<(N + 127) / 128, 256>>>(x, W1, N);

    alpha1_kernel<<<(N * H1 + 255) / 256, 256>>>(a_src1, a_dst1, N);

    edge1_kernel<<<(Etot * 8 + 255) / 256, 256>>>(ei, E, Etot);

    node1_kernel<<<(N * D1 + 255) / 256, 256>>>(b1, N);

    gemm2_kernel<<<(N + 63) / 64, 256>>>(W2, a_src2, a_dst2, N);

    edge2_kernel<<<(Etot * 10 + 255) / 256, 256>>>(ei, E, Etot, out);

    final_kernel<<<(N * OUT + 255) / 256, 256>>>(b2, out, N);
}

// round 4
// speedup vs baseline: 2.8588x; 2.0496x over previous
#include <cuda_runtime.h>

#define F_IN 512
#define H1   8
#define D1   64      // H1*C1
#define OUT  40
#define NMAX 100000
#define EMAX 3200000
#define ETMAX (EMAX + NMAX)
#define NB_SCAN ((NMAX + 255) / 256)   // 391

// ---------------- scratch (device globals: allocation-free) ----------------
__device__ __align__(16) float g_h1 [NMAX * D1];   // x@W1                 [N,64]
__device__ __align__(16) float g_as1[NMAX * H1];
__device__ __align__(16) float g_ad1[NMAX * H1];
__device__ __align__(16) float g_h2 [NMAX * D1];   // elu(layer1 out)
__device__ __align__(16) float g_g2 [NMAX * OUT];  // h2@W2                [N,40]
__device__ __align__(16) float g_as2[NMAX];
__device__ __align__(16) float g_ad2[NMAX];

__device__ int g_deg [NMAX];           // in-degree (incl self loop)
__device__ int g_ptr [NMAX + 1];       // CSR row offsets
__device__ int g_cur [NMAX];           // scatter cursors
__device__ int g_bsum[NB_SCAN];        // per-block degree sums
__device__ int g_boff[NB_SCAN];        // exclusive block offsets
__device__ int g_csr [ETMAX];          // src indices grouped by dst

// ---------------- init: degree = 1 (self loop) ----------------
__global__ void init_kernel(int N) {
    int i = blockIdx.x * blockDim.x + threadIdx.x;
    if (i < N) g_deg[i] = 1;
}

// ---------------- histogram of dst ----------------
__global__ __launch_bounds__(256)
void hist_kernel(const int* __restrict__ ei, int E) {
    int e = blockIdx.x * blockDim.x + threadIdx.x;
    if (e < E) atomicAdd(&g_deg[ei[E + e]], 1);
}

// ---------------- scan phase 1: per-block sums ----------------
__global__ __launch_bounds__(256)
void scan1_kernel(int N) {
    __shared__ int sd[256];
    int n = blockIdx.x * 256 + threadIdx.x;
    int v = (n < N) ? g_deg[n] : 0;
    sd[threadIdx.x] = v;
    __syncthreads();
    for (int off = 1; off < 256; off <<= 1) {
        int t = (threadIdx.x >= off) ? sd[threadIdx.x - off] : 0;
        __syncthreads();
        sd[threadIdx.x] += t;
        __syncthreads();
    }
    if (threadIdx.x == 255) g_bsum[blockIdx.x] = sd[255];
}

// ---------------- scan phase 2: scan block sums (single block) ----------------
__global__ __launch_bounds__(512)
void scan2_kernel(int nb) {
    __shared__ int sd[512];
    int i = threadIdx.x;
    int v = (i < nb) ? g_bsum[i] : 0;
    sd[i] = v;
    __syncthreads();
    for (int off = 1; off < 512; off <<= 1) {
        int t = (i >= off) ? sd[i - off] : 0;
        __syncthreads();
        sd[i] += t;
        __syncthreads();
    }
    if (i < nb) g_boff[i] = sd[i] - v;   // exclusive
}

// ---------------- scan phase 3: final offsets ----------------
__global__ __launch_bounds__(256)
void scan3_kernel(int N, int Etot) {
    __shared__ int sd[256];
    int n = blockIdx.x * 256 + threadIdx.x;
    int v = (n < N) ? g_deg[n] : 0;
    sd[threadIdx.x] = v;
    __syncthreads();
    for (int off = 1; off < 256; off <<= 1) {
        int t = (threadIdx.x >= off) ? sd[threadIdx.x - off] : 0;
        __syncthreads();
        sd[threadIdx.x] += t;
        __syncthreads();
    }
    if (n < N) {
        int p = g_boff[blockIdx.x] + sd[threadIdx.x] - v;  // exclusive
        g_ptr[n] = p;
        g_cur[n] = p;
    }
    if (blockIdx.x == 0 && threadIdx.x == 0) g_ptr[N] = Etot;
}

// ---------------- scatter into CSR ----------------
__global__ __launch_bounds__(256)
void scatter_kernel(const int* __restrict__ ei, int E, int Etot) {
    int e = blockIdx.x * blockDim.x + threadIdx.x;
    if (e >= Etot) return;
    int s, d;
    if (e < E) { s = ei[e]; d = ei[E + e]; }
    else       { s = e - E; d = s; }
    int pos = atomicAdd(&g_cur[d], 1);
    g_csr[pos] = s;
}

// ---------------- GEMM1: h1[N,64] = x[N,512] @ W1[512,64] ----------------
__global__ __launch_bounds__(256)
void gemm1_kernel(const float* __restrict__ x, const float* __restrict__ W, int N) {
    __shared__ float sx[128][33];
    __shared__ float sw[32][64];

    int tid  = threadIdx.x;
    int row0 = blockIdx.x * 128;
    int tx = tid & 15;
    int ty = tid >> 4;

    float acc[8][4];
#pragma unroll
    for (int i = 0; i < 8; i++)
#pragma unroll
        for (int j = 0; j < 4; j++) acc[i][j] = 0.0f;

    int xcg = (tid & 7) * 4;
    int xr  = tid >> 3;
    int wc  = (tid & 15) * 4;
    int wk  = tid >> 4;

    for (int k0 = 0; k0 < F_IN; k0 += 32) {
#pragma unroll
        for (int rr = 0; rr < 4; rr++) {
            int row  = xr + rr * 32;
            int grow = row0 + row;
            float4 v = make_float4(0.f, 0.f, 0.f, 0.f);
            if (grow < N)
                v = *(const float4*)&x[(size_t)grow * F_IN + k0 + xcg];
            sx[row][xcg + 0] = v.x; sx[row][xcg + 1] = v.y;
            sx[row][xcg + 2] = v.z; sx[row][xcg + 3] = v.w;
        }
#pragma unroll
        for (int p = 0; p < 2; p++) {
            int k = wk + p * 16;
            float4 v = *(const float4*)&W[(size_t)(k0 + k) * D1 + wc];
            sw[k][wc + 0] = v.x; sw[k][wc + 1] = v.y;
            sw[k][wc + 2] = v.z; sw[k][wc + 3] = v.w;
        }
        __syncthreads();

#pragma unroll
        for (int kk = 0; kk < 32; kk++) {
            float a[8], b[4];
#pragma unroll
            for (int i = 0; i < 8; i++) a[i] = sx[ty * 8 + i][kk];
#pragma unroll
            for (int j = 0; j < 4; j++) b[j] = sw[kk][tx * 4 + j];
#pragma unroll
            for (int i = 0; i < 8; i++)
#pragma unroll
                for (int j = 0; j < 4; j++) acc[i][j] += a[i] * b[j];
        }
        __syncthreads();
    }

#pragma unroll
    for (int i = 0; i < 8; i++) {
        int grow = row0 + ty * 8 + i;
        if (grow < N) {
#pragma unroll
            for (int j = 0; j < 4; j++)
                g_h1[(size_t)grow * D1 + tx * 4 + j] = acc[i][j];
        }
    }
}

// ---------------- alpha1: per (node, head) dot products ----------------
__global__ void alpha1_kernel(const float* __restrict__ a_src,
                              const float* __restrict__ a_dst, int N) {
    int i = blockIdx.x * blockDim.x + threadIdx.x;
    if (i >= N * H1) return;
    int h = i & 7;
    const float4* hp = (const float4*)&g_h1[(size_t)(i >> 3) * D1 + h * 8];
    float4 v0 = hp[0], v1 = hp[1];
    const float4* asv = (const float4*)&a_src[h * 8];
    const float4* adv = (const float4*)&a_dst[h * 8];
    float4 s0 = asv[0], s1 = asv[1];
    float4 d0 = adv[0], d1 = adv[1];
    g_as1[i] = v0.x * s0.x + v0.y * s0.y + v0.z * s0.z + v0.w * s0.w
             + v1.x * s1.x + v1.y * s1.y + v1.z * s1.z + v1.w * s1.w;
    g_ad1[i] = v0.x * d0.x + v0.y * d0.y + v0.z * d0.z + v0.w * d0.w
             + v1.x * d1.x + v1.y * d1.y + v1.z * d1.z + v1.w * d1.w;
}

// ---------------- gather layer 1: one warp per dst node ----------------
// lane l owns cols {l, l+32}; head_lo = l>>3, head_hi = head_lo+4.
// All lanes of a head compute identical ex -> per-lane den needs no reduce.
// Fuses: softmax-normalize + bias + ELU -> writes g_h2 directly.
__global__ __launch_bounds__(256)
void gather1_kernel(const float* __restrict__ b1, int N) {
    int w = (blockIdx.x * blockDim.x + threadIdx.x) >> 5;
    if (w >= N) return;
    int l   = threadIdx.x & 31;
    int d   = w;
    int beg = g_ptr[d], end = g_ptr[d + 1];
    int hlo = l >> 3, hhi = hlo + 4;

    float ad_lo = g_ad1[d * H1 + hlo];
    float ad_hi = g_ad1[d * H1 + hhi];

    float acc_lo = 0.f, acc_hi = 0.f, den_lo = 0.f, den_hi = 0.f;
    for (int i = beg; i < end; i++) {
        int s = g_csr[i];
        float as_lo = g_as1[s * H1 + hlo];
        float as_hi = g_as1[s * H1 + hhi];
        float tlo = as_lo + ad_lo;  tlo = (tlo > 0.f) ? tlo : 0.2f * tlo;
        float thi = as_hi + ad_hi;  thi = (thi > 0.f) ? thi : 0.2f * thi;
        float exlo = __expf(tlo);
        float exhi = __expf(thi);
        acc_lo += exlo * g_h1[(size_t)s * D1 + l];
        acc_hi += exhi * g_h1[(size_t)s * D1 + 32 + l];
        den_lo += exlo;
        den_hi += exhi;
    }
    float vlo = acc_lo / (den_lo + 1e-16f) + b1[l];
    float vhi = acc_hi / (den_hi + 1e-16f) + b1[32 + l];
    vlo = (vlo > 0.f) ? vlo : (__expf(vlo) - 1.f);
    vhi = (vhi > 0.f) ? vhi : (__expf(vhi) - 1.f);
    g_h2[(size_t)d * D1 + l]      = vlo;
    g_h2[(size_t)d * D1 + 32 + l] = vhi;
}

// ---------------- GEMM2 + alpha2: g2[N,40] = h2[N,64]@W2[64,40] ------------
__global__ __launch_bounds__(256)
void gemm2_kernel(const float* __restrict__ W2,
                  const float* __restrict__ a_src2,
                  const float* __restrict__ a_dst2, int N) {
    __shared__ float sh[64 * 65];
    __shared__ float sw2[64 * OUT];

    int tid = threadIdx.x;
    int n0  = blockIdx.x * 64;

    for (int t = tid; t < 64 * D1; t += 256) {
        int r = t >> 6, c = t & 63;
        int gn = n0 + r;
        sh[r * 65 + c] = (gn < N) ? g_h2[(size_t)gn * D1 + c] : 0.0f;
    }
    for (int t = tid; t < D1 * OUT; t += 256) sw2[t] = W2[t];
    __syncthreads();

    int r = tid >> 2;
    int q = tid & 3;
    float acc[10];
#pragma unroll
    for (int j = 0; j < 10; j++) acc[j] = 0.0f;

#pragma unroll 8
    for (int k = 0; k < D1; k++) {
        float a = sh[r * 65 + k];
#pragma unroll
        for (int j = 0; j < 10; j++)
            acc[j] += a * sw2[k * OUT + q * 10 + j];
    }

    int gn = n0 + r;
    float ps = 0.0f, pd = 0.0f;
#pragma unroll
    for (int j = 0; j < 10; j++) {
        int c = q * 10 + j;
        ps += acc[j] * __ldg(&a_src2[c]);
        pd += acc[j] * __ldg(&a_dst2[c]);
        if (gn < N) g_g2[(size_t)gn * OUT + c] = acc[j];
    }
    ps += __shfl_down_sync(0xffffffffu, ps, 1, 4);
    ps += __shfl_down_sync(0xffffffffu, ps, 2, 4);
    pd += __shfl_down_sync(0xffffffffu, pd, 1, 4);
    pd += __shfl_down_sync(0xffffffffu, pd, 2, 4);
    if (q == 0 && gn < N) { g_as2[gn] = ps; g_ad2[gn] = pd; }
}

// ---------------- gather layer 2: one warp per dst node ----------------
// lane l owns col l; lanes 0-7 also own col 32+l. Writes d_out directly.
__global__ __launch_bounds__(256)
void gather2_kernel(const float* __restrict__ b2, float* __restrict__ out, int N) {
    int w = (blockIdx.x * blockDim.x + threadIdx.x) >> 5;
    if (w >= N) return;
    int l   = threadIdx.x & 31;
    int d   = w;
    int beg = g_ptr[d], end = g_ptr[d + 1];

    float ad = g_ad2[d];
    float acc0 = 0.f, acc1 = 0.f, den = 0.f;
    for (int i = beg; i < end; i++) {
        int s = g_csr[i];
        float t = g_as2[s] + ad;
        t = (t > 0.f) ? t : 0.2f * t;
        float ex = __expf(t);
        acc0 += ex * g_g2[(size_t)s * OUT + l];
        if (l < 8) acc1 += ex * g_g2[(size_t)s * OUT + 32 + l];
        den += ex;
    }
    float inv = 1.0f / (den + 1e-16f);
    out[(size_t)d * OUT + l] = acc0 * inv + b2[l];
    if (l < 8)
        out[(size_t)d * OUT + 32 + l] = acc1 * inv + b2[32 + l];
}

// ---------------- launch ----------------
extern "C" void kernel_launch(void* const* d_in, const int* in_sizes, int n_in,
                              void* d_out, int out_size) {
    const float* x      = (const float*)d_in[0];
    const int*   ei     = (const int*)d_in[1];   // int32 edge index
    const float* W1     = (const float*)d_in[2];
    const float* a_src1 = (const float*)d_in[3];
    const float* a_dst1 = (const float*)d_in[4];
    const float* b1     = (const float*)d_in[5];
    const float* W2     = (const float*)d_in[6];
    const float* a_src2 = (const float*)d_in[7];
    const float* a_dst2 = (const float*)d_in[8];
    const float* b2     = (const float*)d_in[9];
    float* out = (float*)d_out;

    int N    = in_sizes[0] / F_IN;       // 100000
    int E    = in_sizes[1] / 2;          // 3200000
    int Etot = E + N;
    int nb   = (N + 255) / 256;

    // CSR build (also overlappable with gemm1 on the same stream order)
    init_kernel<<<(N + 255) / 256, 256>>>(N);
    hist_kernel<<<(E + 255) / 256, 256>>>(ei, E);
    scan1_kernel<<<nb, 256>>>(N);
    scan2_kernel<<<1, 512>>>(nb);
    scan3_kernel<<<nb, 256>>>(N, Etot);
    scatter_kernel<<<(Etot + 255) / 256, 256>>>(ei, E, Etot);

    gemm1_kernel<<<(N + 127) / 128, 256>>>(x, W1, N);
    alpha1_kernel<<<(N * H1 + 255) / 256, 256>>>(a_src1, a_dst1, N);

    gather1_kernel<<<(N * 32 + 255) / 256, 256>>>(b1, N);

    gemm2_kernel<<<(N + 63) / 64, 256>>>(W2, a_src2, a_dst2, N);

    gather2_kernel<<<(N * 32 + 255) / 256, 256>>>(b2, out, N);
}

// round 5
// speedup vs baseline: 3.0503x; 1.0670x over previous
#include <cuda_runtime.h>
#include <cstdint>

#define F_IN 512
#define H1   8
#define D1   64      // H1*C1
#define OUT  40
#define NMAX 100000
#define EMAX 3200000
#define ETMAX (EMAX + NMAX)
#define NB_SCAN ((NMAX + 255) / 256)   // 391

// ---------------- scratch (device globals: allocation-free) ----------------
__device__ __align__(16) float g_h1 [NMAX * D1];   // x@W1                 [N,64]
__device__ __align__(16) float g_as1[NMAX * H1];
__device__ __align__(16) float g_ad1[NMAX * H1];
__device__ __align__(16) float g_h2 [NMAX * D1];   // elu(layer1 out)
__device__ __align__(16) float g_g2 [NMAX * OUT];  // h2@W2                [N,40]
__device__ __align__(16) float g_as2[NMAX];
__device__ __align__(16) float g_ad2[NMAX];
__device__ __align__(16) float g_wT [D1 * F_IN];   // W1^T  [64][512]

__device__ int g_deg [NMAX];
__device__ int g_ptr [NMAX + 1];
__device__ int g_cur [NMAX];
__device__ int g_bsum[NB_SCAN];
__device__ int g_boff[NB_SCAN];
__device__ int g_csr [ETMAX];

// ---------------- tf32 helpers ----------------
__device__ __forceinline__ uint32_t f2tf(float x) {
    uint32_t r;
    asm("cvt.rna.tf32.f32 %0, %1;" : "=r"(r) : "f"(x));
    return r;
}
__device__ __forceinline__ void mma_tf32(float c[4],
                                         uint32_t a0, uint32_t a1, uint32_t a2, uint32_t a3,
                                         uint32_t b0, uint32_t b1) {
    asm volatile("mma.sync.aligned.m16n8k8.row.col.f32.tf32.tf32.f32 "
                 "{%0,%1,%2,%3}, {%4,%5,%6,%7}, {%8,%9}, {%0,%1,%2,%3};"
                 : "+f"(c[0]), "+f"(c[1]), "+f"(c[2]), "+f"(c[3])
                 : "r"(a0), "r"(a1), "r"(a2), "r"(a3), "r"(b0), "r"(b1));
}

// ---------------- CSR build ----------------
__global__ void init_kernel(int N) {
    int i = blockIdx.x * blockDim.x + threadIdx.x;
    if (i < N) g_deg[i] = 1;
}
__global__ __launch_bounds__(256)
void hist_kernel(const int* __restrict__ ei, int E) {
    int e = blockIdx.x * blockDim.x + threadIdx.x;
    if (e < E) atomicAdd(&g_deg[ei[E + e]], 1);
}
__global__ __launch_bounds__(256)
void scan1_kernel(int N) {
    __shared__ int sd[256];
    int n = blockIdx.x * 256 + threadIdx.x;
    int v = (n < N) ? g_deg[n] : 0;
    sd[threadIdx.x] = v;
    __syncthreads();
    for (int off = 1; off < 256; off <<= 1) {
        int t = (threadIdx.x >= off) ? sd[threadIdx.x - off] : 0;
        __syncthreads();
        sd[threadIdx.x] += t;
        __syncthreads();
    }
    if (threadIdx.x == 255) g_bsum[blockIdx.x] = sd[255];
}
__global__ __launch_bounds__(512)
void scan2_kernel(int nb) {
    __shared__ int sd[512];
    int i = threadIdx.x;
    int v = (i < nb) ? g_bsum[i] : 0;
    sd[i] = v;
    __syncthreads();
    for (int off = 1; off < 512; off <<= 1) {
        int t = (i >= off) ? sd[i - off] : 0;
        __syncthreads();
        sd[i] += t;
        __syncthreads();
    }
    if (i < nb) g_boff[i] = sd[i] - v;
}
__global__ __launch_bounds__(256)
void scan3_kernel(int N, int Etot) {
    __shared__ int sd[256];
    int n = blockIdx.x * 256 + threadIdx.x;
    int v = (n < N) ? g_deg[n] : 0;
    sd[threadIdx.x] = v;
    __syncthreads();
    for (int off = 1; off < 256; off <<= 1) {
        int t = (threadIdx.x >= off) ? sd[threadIdx.x - off] : 0;
        __syncthreads();
        sd[threadIdx.x] += t;
        __syncthreads();
    }
    if (n < N) {
        int p = g_boff[blockIdx.x] + sd[threadIdx.x] - v;
        g_ptr[n] = p;
        g_cur[n] = p;
    }
    if (blockIdx.x == 0 && threadIdx.x == 0) g_ptr[N] = Etot;
}
__global__ __launch_bounds__(256)
void scatter_kernel(const int* __restrict__ ei, int E, int Etot) {
    int e = blockIdx.x * blockDim.x + threadIdx.x;
    if (e >= Etot) return;
    int s, d;
    if (e < E) { s = ei[e]; d = ei[E + e]; }
    else       { s = e - E; d = s; }
    int pos = atomicAdd(&g_cur[d], 1);
    g_csr[pos] = s;
}

// ---------------- transpose W1 -> wT[64][512] ----------------
__global__ void wt_kernel(const float* __restrict__ W) {
    int i = blockIdx.x * blockDim.x + threadIdx.x;
    if (i >= F_IN * D1) return;
    int k = i >> 6, n = i & 63;
    g_wT[n * F_IN + k] = W[i];
}

// ---------------- GEMM1 (3xTF32 tensor core) ----------------
// h1[N,64] = x[N,512] @ W1[512,64]. Block tile 128x64, BK=32, 8 warps (4m x 2n),
// warp tile 32x32 = 2 x (m16) x 4 x (n8), k in 4 steps of 8.
__global__ __launch_bounds__(256)
void gemm1_kernel(const float* __restrict__ x, int N) {
    __shared__ float sx [128][36];   // stride 36: 4r+k distinct mod 32
    __shared__ float swT[64][36];

    int tid  = threadIdx.x;
    int wid  = tid >> 5;
    int l    = tid & 31;
    int gid  = l >> 2;      // group id (0..7)
    int tig  = l & 3;       // thread-in-group
    int row0 = blockIdx.x * 128;
    int warp_m = (wid >> 1) * 32;
    int warp_n = (wid & 1) * 32;

    float acc[2][4][4];
#pragma unroll
    for (int mt = 0; mt < 2; mt++)
#pragma unroll
        for (int nt = 0; nt < 4; nt++)
#pragma unroll
            for (int r = 0; r < 4; r++) acc[mt][nt][r] = 0.0f;

    for (int k0 = 0; k0 < F_IN; k0 += 32) {
        // load x tile [128 x 32] (float4, coalesced)
#pragma unroll
        for (int i = 0; i < 4; i++) {
            int lin = tid + i * 256;
            int row = lin >> 3, kq = lin & 7;
            int grow = row0 + row;
            float4 v = make_float4(0.f, 0.f, 0.f, 0.f);
            if (grow < N)
                v = *(const float4*)&x[(size_t)grow * F_IN + k0 + kq * 4];
            *(float4*)&sx[row][kq * 4] = v;
        }
        // load wT tile [64 x 32]
#pragma unroll
        for (int i = 0; i < 2; i++) {
            int lin = tid + i * 256;
            int n = lin >> 3, kq = lin & 7;
            float4 v = *(const float4*)&g_wT[n * F_IN + k0 + kq * 4];
            *(float4*)&swT[n][kq * 4] = v;
        }
        __syncthreads();

#pragma unroll
        for (int ks = 0; ks < 4; ks++) {
            int kb = ks * 8;
            // A fragments (hi/lo)
            uint32_t ah[2][4], al[2][4];
#pragma unroll
            for (int mt = 0; mt < 2; mt++) {
                int rb = warp_m + mt * 16 + gid;
                float a0 = sx[rb][kb + tig];
                float a1 = sx[rb + 8][kb + tig];
                float a2 = sx[rb][kb + tig + 4];
                float a3 = sx[rb + 8][kb + tig + 4];
                ah[mt][0] = f2tf(a0); al[mt][0] = __float_as_uint(a0 - __uint_as_float(ah[mt][0]));
                ah[mt][1] = f2tf(a1); al[mt][1] = __float_as_uint(a1 - __uint_as_float(ah[mt][1]));
                ah[mt][2] = f2tf(a2); al[mt][2] = __float_as_uint(a2 - __uint_as_float(ah[mt][2]));
                ah[mt][3] = f2tf(a3); al[mt][3] = __float_as_uint(a3 - __uint_as_float(ah[mt][3]));
            }
            // B fragments (hi/lo)
            uint32_t bh[4][2], bl[4][2];
#pragma unroll
            for (int nt = 0; nt < 4; nt++) {
                int nb = warp_n + nt * 8 + gid;
                float b0 = swT[nb][kb + tig];
                float b1 = swT[nb][kb + tig + 4];
                bh[nt][0] = f2tf(b0); bl[nt][0] = __float_as_uint(b0 - __uint_as_float(bh[nt][0]));
                bh[nt][1] = f2tf(b1); bl[nt][1] = __float_as_uint(b1 - __uint_as_float(bh[nt][1]));
            }
#pragma unroll
            for (int mt = 0; mt < 2; mt++)
#pragma unroll
                for (int nt = 0; nt < 4; nt++) {
                    mma_tf32(acc[mt][nt], ah[mt][0], ah[mt][1], ah[mt][2], ah[mt][3],
                             bh[nt][0], bh[nt][1]);
                    mma_tf32(acc[mt][nt], al[mt][0], al[mt][1], al[mt][2], al[mt][3],
                             bh[nt][0], bh[nt][1]);
                    mma_tf32(acc[mt][nt], ah[mt][0], ah[mt][1], ah[mt][2], ah[mt][3],
                             bl[nt][0], bl[nt][1]);
                }
        }
        __syncthreads();
    }

    // epilogue: c0,c1 -> row gid, cols 2*tig,+1 ; c2,c3 -> row gid+8
#pragma unroll
    for (int mt = 0; mt < 2; mt++) {
        int r0 = row0 + warp_m + mt * 16 + gid;
        int r1 = r0 + 8;
#pragma unroll
        for (int nt = 0; nt < 4; nt++) {
            int col = warp_n + nt * 8 + 2 * tig;
            if (r0 < N) *(float2*)&g_h1[(size_t)r0 * D1 + col]
                            = make_float2(acc[mt][nt][0], acc[mt][nt][1]);
            if (r1 < N) *(float2*)&g_h1[(size_t)r1 * D1 + col]
                            = make_float2(acc[mt][nt][2], acc[mt][nt][3]);
        }
    }
}

// ---------------- alpha1: per (node, head) dot products ----------------
__global__ void alpha1_kernel(const float* __restrict__ a_src,
                              const float* __restrict__ a_dst, int N) {
    int i = blockIdx.x * blockDim.x + threadIdx.x;
    if (i >= N * H1) return;
    int h = i & 7;
    const float4* hp = (const float4*)&g_h1[(size_t)(i >> 3) * D1 + h * 8];
    float4 v0 = hp[0], v1 = hp[1];
    const float4* asv = (const float4*)&a_src[h * 8];
    const float4* adv = (const float4*)&a_dst[h * 8];
    float4 s0 = asv[0], s1 = asv[1];
    float4 d0 = adv[0], d1 = adv[1];
    g_as1[i] = v0.x * s0.x + v0.y * s0.y + v0.z * s0.z + v0.w * s0.w
             + v1.x * s1.x + v1.y * s1.y + v1.z * s1.z + v1.w * s1.w;
    g_ad1[i] = v0.x * d0.x + v0.y * d0.y + v0.z * d0.z + v0.w * d0.w
             + v1.x * d1.x + v1.y * d1.y + v1.z * d1.z + v1.w * d1.w;
}

// ---------------- gather layer 1: one warp per dst node ----------------
__global__ __launch_bounds__(256)
void gather1_kernel(const float* __restrict__ b1, int N) {
    int w = (blockIdx.x * blockDim.x + threadIdx.x) >> 5;
    if (w >= N) return;
    int l   = threadIdx.x & 31;
    int d   = w;
    int beg = g_ptr[d], end = g_ptr[d + 1];
    int hlo = l >> 3, hhi = hlo + 4;

    float ad_lo = g_ad1[d * H1 + hlo];
    float ad_hi = g_ad1[d * H1 + hhi];

    float acc_lo = 0.f, acc_hi = 0.f, den_lo = 0.f, den_hi = 0.f;
    for (int i = beg; i < end; i++) {
        int s = g_csr[i];
        float as_lo = g_as1[s * H1 + hlo];
        float as_hi = g_as1[s * H1 + hhi];
        float tlo = as_lo + ad_lo;  tlo = (tlo > 0.f) ? tlo : 0.2f * tlo;
        float thi = as_hi + ad_hi;  thi = (thi > 0.f) ? thi : 0.2f * thi;
        float exlo = __expf(tlo);
        float exhi = __expf(thi);
        acc_lo += exlo * g_h1[(size_t)s * D1 + l];
        acc_hi += exhi * g_h1[(size_t)s * D1 + 32 + l];
        den_lo += exlo;
        den_hi += exhi;
    }
    float vlo = acc_lo / (den_lo + 1e-16f) + b1[l];
    float vhi = acc_hi / (den_hi + 1e-16f) + b1[32 + l];
    vlo = (vlo > 0.f) ? vlo : (__expf(vlo) - 1.f);
    vhi = (vhi > 0.f) ? vhi : (__expf(vhi) - 1.f);
    g_h2[(size_t)d * D1 + l]      = vlo;
    g_h2[(size_t)d * D1 + 32 + l] = vhi;
}

// ---------------- GEMM2 + alpha2: g2[N,40] = h2[N,64]@W2[64,40] ------------
__global__ __launch_bounds__(256)
void gemm2_kernel(const float* __restrict__ W2,
                  const float* __restrict__ a_src2,
                  const float* __restrict__ a_dst2, int N) {
    __shared__ float sh[64 * 65];
    __shared__ float sw2[64 * OUT];

    int tid = threadIdx.x;
    int n0  = blockIdx.x * 64;

    for (int t = tid; t < 64 * D1; t += 256) {
        int r = t >> 6, c = t & 63;
        int gn = n0 + r;
        sh[r * 65 + c] = (gn < N) ? g_h2[(size_t)gn * D1 + c] : 0.0f;
    }
    for (int t = tid; t < D1 * OUT; t += 256) sw2[t] = W2[t];
    __syncthreads();

    int r = tid >> 2;
    int q = tid & 3;
    float acc[10];
#pragma unroll
    for (int j = 0; j < 10; j++) acc[j] = 0.0f;

#pragma unroll 8
    for (int k = 0; k < D1; k++) {
        float a = sh[r * 65 + k];
#pragma unroll
        for (int j = 0; j < 10; j++)
            acc[j] += a * sw2[k * OUT + q * 10 + j];
    }

    int gn = n0 + r;
    float ps = 0.0f, pd = 0.0f;
#pragma unroll
    for (int j = 0; j < 10; j++) {
        int c = q * 10 + j;
        ps += acc[j] * __ldg(&a_src2[c]);
        pd += acc[j] * __ldg(&a_dst2[c]);
        if (gn < N) g_g2[(size_t)gn * OUT + c] = acc[j];
    }
    ps += __shfl_down_sync(0xffffffffu, ps, 1, 4);
    ps += __shfl_down_sync(0xffffffffu, ps, 2, 4);
    pd += __shfl_down_sync(0xffffffffu, pd, 1, 4);
    pd += __shfl_down_sync(0xffffffffu, pd, 2, 4);
    if (q == 0 && gn < N) { g_as2[gn] = ps; g_ad2[gn] = pd; }
}

// ---------------- gather layer 2: one warp per dst node ----------------
__global__ __launch_bounds__(256)
void gather2_kernel(const float* __restrict__ b2, float* __restrict__ out, int N) {
    int w = (blockIdx.x * blockDim.x + threadIdx.x) >> 5;
    if (w >= N) return;
    int l   = threadIdx.x & 31;
    int d   = w;
    int beg = g_ptr[d], end = g_ptr[d + 1];

    float ad = g_ad2[d];
    float acc0 = 0.f, acc1 = 0.f, den = 0.f;
    for (int i = beg; i < end; i++) {
        int s = g_csr[i];
        float t = g_as2[s] + ad;
        t = (t > 0.f) ? t : 0.2f * t;
        float ex = __expf(t);
        acc0 += ex * g_g2[(size_t)s * OUT + l];
        if (l < 8) acc1 += ex * g_g2[(size_t)s * OUT + 32 + l];
        den += ex;
    }
    float inv = 1.0f / (den + 1e-16f);
    out[(size_t)d * OUT + l] = acc0 * inv + b2[l];
    if (l < 8)
        out[(size_t)d * OUT + 32 + l] = acc1 * inv + b2[32 + l];
}

// ---------------- launch ----------------
extern "C" void kernel_launch(void* const* d_in, const int* in_sizes, int n_in,
                              void* d_out, int out_size) {
    const float* x      = (const float*)d_in[0];
    const int*   ei     = (const int*)d_in[1];
    const float* W1     = (const float*)d_in[2];
    const float* a_src1 = (const float*)d_in[3];
    const float* a_dst1 = (const float*)d_in[4];
    const float* b1     = (const float*)d_in[5];
    const float* W2     = (const float*)d_in[6];
    const float* a_src2 = (const float*)d_in[7];
    const float* a_dst2 = (const float*)d_in[8];
    const float* b2     = (const float*)d_in[9];
    float* out = (float*)d_out;

    int N    = in_sizes[0] / F_IN;       // 100000
    int E    = in_sizes[1] / 2;          // 3200000
    int Etot = E + N;
    int nb   = (N + 255) / 256;

    // CSR build
    init_kernel<<<(N + 255) / 256, 256>>>(N);
    hist_kernel<<<(E + 255) / 256, 256>>>(ei, E);
    scan1_kernel<<<nb, 256>>>(N);
    scan2_kernel<<<1, 512>>>(nb);
    scan3_kernel<<<nb, 256>>>(N, Etot);
    scatter_kernel<<<(Etot + 255) / 256, 256>>>(ei, E, Etot);

    wt_kernel<<<(F_IN * D1 + 255) / 256, 256>>>(W1);
    gemm1_kernel<<<(N + 127) / 128, 256>>>(x, N);
    alpha1_kernel<<<(N * H1 + 255) / 256, 256>>>(a_src1, a_dst1, N);

    gather1_kernel<<<(N * 32 + 255) / 256, 256>>>(b1, N);

    gemm2_kernel<<<(N + 63) / 64, 256>>>(W2, a_src2, a_dst2, N);

    gather2_kernel<<<(N * 32 + 255) / 256, 256>>>(b2, out, N);
}